// round 1
// baseline (speedup 1.0000x reference)
#include <cuda_runtime.h>
#include <cuda_bf16.h>
#include <math.h>

#define Bq 4
#define Sq 2048
#define DIN 64
#define Dq 512
#define Hq 8
#define Lq 2
#define NCq 2
#define DKq 64
#define TOPKq 35

#define FLAG_RELU 1
#define FLAG_PE 2

// ---------------- scratch (device globals; no runtime allocation) ----------------
__device__ float g_h [Bq*Sq*Dq];
__device__ float g_q [Bq*Sq*Dq];
__device__ float g_k [Bq*Sq*Dq];
__device__ float g_v [Bq*Sq*Dq];
__device__ float g_ao[Bq*Sq*Dq];
__device__ float g_tmp[Bq*Sq*Dq];
__device__ float g_ff[Bq*Sq*4*Dq];
__device__ float g_scores[(size_t)Bq*Hq*Sq*Sq];   // 512 MB
__device__ float g_pool[Bq*Dq];

// ---------------- generic fp32 GEMM: C = A[M,K] @ W[K,N] + bias, opt relu / +PE ----------------
__global__ void __launch_bounds__(256) gemm_kernel(
    const float* __restrict__ A, const float* __restrict__ W,
    const float* __restrict__ bias, float* __restrict__ C,
    int M, int N, int K, int flags)
{
    __shared__ float As[64][16];
    __shared__ float Ws[16][64];
    int tid = threadIdx.x;
    int tx = tid & 15, ty = tid >> 4;
    int row0 = blockIdx.y * 64, col0 = blockIdx.x * 64;
    int ar = tid >> 2, ac = (tid & 3) << 2;      // A tile slot
    int wr = tid >> 4, wc = (tid & 15) << 2;     // W tile slot
    float acc[4][4] = {};
    for (int k0 = 0; k0 < K; k0 += 16) {
        float4 av = *(const float4*)&A[(size_t)(row0 + ar) * K + k0 + ac];
        As[ar][ac] = av.x; As[ar][ac+1] = av.y; As[ar][ac+2] = av.z; As[ar][ac+3] = av.w;
        float4 wv = *(const float4*)&W[(size_t)(k0 + wr) * N + col0 + wc];
        *(float4*)&Ws[wr][wc] = wv;
        __syncthreads();
        #pragma unroll
        for (int kk = 0; kk < 16; kk++) {
            float a[4], b[4];
            #pragma unroll
            for (int i = 0; i < 4; i++) a[i] = As[ty*4 + i][kk];
            #pragma unroll
            for (int j = 0; j < 4; j++) b[j] = Ws[kk][tx*4 + j];
            #pragma unroll
            for (int i = 0; i < 4; i++)
                #pragma unroll
                for (int j = 0; j < 4; j++)
                    acc[i][j] += a[i] * b[j];
        }
        __syncthreads();
    }
    #pragma unroll
    for (int i = 0; i < 4; i++) {
        int r = row0 + ty*4 + i;
        #pragma unroll
        for (int j = 0; j < 4; j++) {
            int c = col0 + tx*4 + j;
            float v = acc[i][j] + bias[c];
            if (flags & FLAG_RELU) v = fmaxf(v, 0.0f);
            if (flags & FLAG_PE) {
                int s = r % Sq;
                int half = c >> 1;
                // replicate reference fp32 roundings, but keep sin/cos range
                // reduction in double (fast-math __sinf would be wrong at arg~2047)
                double e = exp((double)(2 * half) * (-9.210340371976184 / 512.0));
                float divf = (float)e;
                float argf = (float)s * divf;
                float pev = (c & 1) ? (float)cos((double)argf) : (float)sin((double)argf);
                v += pev;
            }
            C[(size_t)r * N + c] = v;
        }
    }
}

// ---------------- scores: per (b,h)  C[S,S] = q @ k^T * scale ----------------
__global__ void __launch_bounds__(256) scores_kernel(
    const float* __restrict__ q, const float* __restrict__ k,
    float* __restrict__ scores)
{
    __shared__ float Qs[64][65];
    __shared__ float Ks[64][65];
    int z = blockIdx.z;
    int b = z / Hq, h = z % Hq;
    const float* qb = q + (size_t)b * Sq * Dq + h * DKq;
    const float* kb = k + (size_t)b * Sq * Dq + h * DKq;
    int q0 = blockIdx.y * 64, k0 = blockIdx.x * 64;
    int tid = threadIdx.x;
    #pragma unroll
    for (int t = 0; t < 4; t++) {
        int slot = tid + t * 256;            // 1024 float4 slots for 64x64
        int row = slot >> 4, c4 = (slot & 15) << 2;
        float4 qv = *(const float4*)&qb[(size_t)(q0 + row) * Dq + c4];
        Qs[row][c4] = qv.x; Qs[row][c4+1] = qv.y; Qs[row][c4+2] = qv.z; Qs[row][c4+3] = qv.w;
        float4 kv = *(const float4*)&kb[(size_t)(k0 + row) * Dq + c4];
        Ks[row][c4] = kv.x; Ks[row][c4+1] = kv.y; Ks[row][c4+2] = kv.z; Ks[row][c4+3] = kv.w;
    }
    __syncthreads();
    int tx = tid & 15, ty = tid >> 4;
    float acc[4][4] = {};
    #pragma unroll 8
    for (int d = 0; d < 64; d++) {
        float a[4], bb[4];
        #pragma unroll
        for (int i = 0; i < 4; i++) a[i]  = Qs[ty*4 + i][d];
        #pragma unroll
        for (int j = 0; j < 4; j++) bb[j] = Ks[tx*4 + j][d];
        #pragma unroll
        for (int i = 0; i < 4; i++)
            #pragma unroll
            for (int j = 0; j < 4; j++)
                acc[i][j] += a[i] * bb[j];
    }
    float* dst = scores + (size_t)z * Sq * Sq;
    #pragma unroll
    for (int i = 0; i < 4; i++)
        #pragma unroll
        for (int j = 0; j < 4; j++)
            dst[(size_t)(q0 + ty*4 + i) * Sq + k0 + tx*4 + j] = acc[i][j] * 0.125f;
}

// ---------------- top-k (k=35, descending, smallest-index ties) + softmax + A@V[:35] ----------------
// one warp per query row; 4 warps / block
__global__ void __launch_bounds__(128) topk_attn_kernel(
    const float* __restrict__ scores, const float* __restrict__ v,
    float* __restrict__ ao)
{
    __shared__ float srow[4][Sq];
    __shared__ float tv[4][TOPKq];
    int w = threadIdx.x >> 5, lane = threadIdx.x & 31;
    int r = blockIdx.x * 4 + w;              // r = (b*H + h)*S + qq
    int qq = r % Sq;
    int h  = (r / Sq) % Hq;
    int b  = r / (Sq * Hq);
    const float* src = scores + (size_t)r * Sq;
    for (int i = lane; i < Sq; i += 32) srow[w][i] = src[i];
    __syncwarp();

    for (int it = 0; it < TOPKq; it++) {
        float best = -INFINITY; int bidx = Sq;
        #pragma unroll 8
        for (int i = 0; i < Sq / 32; i++) {
            int idx = i * 32 + lane;
            float val = srow[w][idx];
            if (val > best) { best = val; bidx = idx; }   // strict > keeps smallest idx
        }
        #pragma unroll
        for (int off = 16; off; off >>= 1) {
            float ov = __shfl_down_sync(0xffffffffu, best, off);
            int   oi = __shfl_down_sync(0xffffffffu, bidx, off);
            if (ov > best || (ov == best && oi < bidx)) { best = ov; bidx = oi; }
        }
        bidx = __shfl_sync(0xffffffffu, bidx, 0);
        best = __shfl_sync(0xffffffffu, best, 0);
        if (lane == 0) { tv[w][it] = best; srow[w][bidx] = -INFINITY; }
        __syncwarp();
    }

    // softmax over sorted top-k (max = tv[0] since extraction is descending)
    float m = tv[w][0];
    float lsum = 0.0f;
    for (int j = lane; j < TOPKq; j += 32) {
        float e = expf(tv[w][j] - m);
        tv[w][j] = e;
        lsum += e;
    }
    __syncwarp();
    #pragma unroll
    for (int off = 16; off; off >>= 1) lsum += __shfl_xor_sync(0xffffffffu, lsum, off);
    float inv = 1.0f / lsum;

    // ao[d] = sum_j attn[j] * v[b, j, h*64 + d]   (V's FIRST 35 rows — source quirk)
    const float* vb = v + (size_t)b * Sq * Dq + h * DKq;
    float a0 = 0.0f, a1 = 0.0f;
    #pragma unroll
    for (int j = 0; j < TOPKq; j++) {
        float a = tv[w][j];
        a0 += a * vb[(size_t)j * Dq + lane];
        a1 += a * vb[(size_t)j * Dq + lane + 32];
    }
    float* dst = ao + (size_t)(b * Sq + qq) * Dq + h * DKq;
    dst[lane]      = a0 * inv;
    dst[lane + 32] = a1 * inv;
}

// ---------------- h = LN(h + add) ----------------
__global__ void __launch_bounds__(128) add_ln_kernel(
    float* __restrict__ hbuf, const float* __restrict__ add,
    const float* __restrict__ g, const float* __restrict__ bta)
{
    int row = blockIdx.x;
    int tid = threadIdx.x;
    const float* hr = hbuf + (size_t)row * Dq;
    const float* ar = add  + (size_t)row * Dq;
    float x[4];
    float s = 0.0f, s2 = 0.0f;
    #pragma unroll
    for (int i = 0; i < 4; i++) {
        float v = hr[tid + i * 128] + ar[tid + i * 128];
        x[i] = v; s += v; s2 += v * v;
    }
    __shared__ float rs[4], rs2[4];
    #pragma unroll
    for (int off = 16; off; off >>= 1) {
        s  += __shfl_xor_sync(0xffffffffu, s, off);
        s2 += __shfl_xor_sync(0xffffffffu, s2, off);
    }
    if ((tid & 31) == 0) { rs[tid >> 5] = s; rs2[tid >> 5] = s2; }
    __syncthreads();
    s  = rs[0] + rs[1] + rs[2] + rs[3];
    s2 = rs2[0] + rs2[1] + rs2[2] + rs2[3];
    float mean = s * (1.0f / Dq);
    float var  = s2 * (1.0f / Dq) - mean * mean;
    float invs = rsqrtf(var + 1e-5f);
    float* out = hbuf + (size_t)row * Dq;
    #pragma unroll
    for (int i = 0; i < 4; i++) {
        int c = tid + i * 128;
        out[c] = (x[i] - mean) * invs * g[c] + bta[c];
    }
}

// ---------------- pooled[b,d] = mean_s h[b,s,d] ----------------
__global__ void pool_kernel(const float* __restrict__ h, float* __restrict__ pool)
{
    int idx = blockIdx.x * blockDim.x + threadIdx.x;
    if (idx >= Bq * Dq) return;
    int b = idx / Dq, d = idx % Dq;
    const float* p = h + (size_t)b * Sq * Dq + d;
    double s = 0.0;
    for (int i = 0; i < Sq; i++) s += p[(size_t)i * Dq];
    pool[idx] = (float)(s * (1.0 / Sq));
}

// ---------------- decoder: out = relu(pool@W1+b1)@W2+b2 ----------------
__global__ void __launch_bounds__(256) decoder_kernel(
    const float* __restrict__ pool,
    const float* __restrict__ w1, const float* __restrict__ b1,
    const float* __restrict__ w2, const float* __restrict__ b2,
    float* __restrict__ out)
{
    __shared__ float ps[Bq * Dq];
    __shared__ float tmp[Bq * 256];
    int tid = threadIdx.x;
    for (int i = tid; i < Bq * Dq; i += 256) ps[i] = pool[i];
    __syncthreads();
    #pragma unroll
    for (int e = 0; e < 4; e++) {
        int idx = tid + e * 256;             // 4*256 = 1024 hidden entries
        int bi = idx >> 8, j = idx & 255;
        float acc = b1[j];
        for (int k = 0; k < Dq; k++) acc += ps[bi * Dq + k] * w1[k * 256 + j];
        tmp[idx] = fmaxf(acc, 0.0f);
    }
    __syncthreads();
    if (tid < Bq * NCq) {
        int bi = tid / NCq, c = tid % NCq;
        float acc = b2[c];
        for (int j = 0; j < 256; j++) acc += tmp[bi * 256 + j] * w2[j * NCq + c];
        out[tid] = acc;
    }
}

// ---------------- launch ----------------
extern "C" void kernel_launch(void* const* d_in, const int* in_sizes, int n_in,
                              void* d_out, int out_size)
{
    const float* x      = (const float*)d_in[0];
    const float* emb_w  = (const float*)d_in[1];
    const float* emb_b  = (const float*)d_in[2];
    const float* wq     = (const float*)d_in[3];
    const float* bq     = (const float*)d_in[4];
    const float* wk     = (const float*)d_in[5];
    const float* bk     = (const float*)d_in[6];
    const float* wv     = (const float*)d_in[7];
    const float* bv     = (const float*)d_in[8];
    const float* wo     = (const float*)d_in[9];
    const float* bo     = (const float*)d_in[10];
    const float* ff1_w  = (const float*)d_in[11];
    const float* ff1_b  = (const float*)d_in[12];
    const float* ff2_w  = (const float*)d_in[13];
    const float* ff2_b  = (const float*)d_in[14];
    const float* ln1_g  = (const float*)d_in[15];
    const float* ln1_b  = (const float*)d_in[16];
    const float* ln2_g  = (const float*)d_in[17];
    const float* ln2_b  = (const float*)d_in[18];
    const float* dec1_w = (const float*)d_in[19];
    const float* dec1_b = (const float*)d_in[20];
    const float* dec2_w = (const float*)d_in[21];
    const float* dec2_b = (const float*)d_in[22];
    float* out = (float*)d_out;

    float *h, *q, *k, *v, *ao, *tmp, *ff, *sc, *pl;
    cudaGetSymbolAddress((void**)&h,   g_h);
    cudaGetSymbolAddress((void**)&q,   g_q);
    cudaGetSymbolAddress((void**)&k,   g_k);
    cudaGetSymbolAddress((void**)&v,   g_v);
    cudaGetSymbolAddress((void**)&ao,  g_ao);
    cudaGetSymbolAddress((void**)&tmp, g_tmp);
    cudaGetSymbolAddress((void**)&ff,  g_ff);
    cudaGetSymbolAddress((void**)&sc,  g_scores);
    cudaGetSymbolAddress((void**)&pl,  g_pool);

    const int M = Bq * Sq;   // 8192

    // embedding + positional encoding
    gemm_kernel<<<dim3(Dq / 64, M / 64), 256>>>(x, emb_w, emb_b, h, M, Dq, DIN, FLAG_PE);

    for (int l = 0; l < Lq; l++) {
        const float* wq_l = wq + (size_t)l * Dq * Dq;
        const float* wk_l = wk + (size_t)l * Dq * Dq;
        const float* wv_l = wv + (size_t)l * Dq * Dq;
        const float* wo_l = wo + (size_t)l * Dq * Dq;
        const float* bq_l = bq + l * Dq;
        const float* bk_l = bk + l * Dq;
        const float* bv_l = bv + l * Dq;
        const float* bo_l = bo + l * Dq;
        const float* f1w  = ff1_w + (size_t)l * Dq * 4 * Dq;
        const float* f1b  = ff1_b + l * 4 * Dq;
        const float* f2w  = ff2_w + (size_t)l * 4 * Dq * Dq;
        const float* f2b  = ff2_b + l * Dq;

        gemm_kernel<<<dim3(Dq / 64, M / 64), 256>>>(h, wq_l, bq_l, q, M, Dq, Dq, 0);
        gemm_kernel<<<dim3(Dq / 64, M / 64), 256>>>(h, wk_l, bk_l, k, M, Dq, Dq, 0);
        gemm_kernel<<<dim3(Dq / 64, M / 64), 256>>>(h, wv_l, bv_l, v, M, Dq, Dq, 0);

        scores_kernel<<<dim3(Sq / 64, Sq / 64, Bq * Hq), 256>>>(q, k, sc);
        topk_attn_kernel<<<(Bq * Hq * Sq) / 4, 128>>>(sc, v, ao);

        gemm_kernel<<<dim3(Dq / 64, M / 64), 256>>>(ao, wo_l, bo_l, tmp, M, Dq, Dq, 0);
        add_ln_kernel<<<M, 128>>>(h, tmp, ln1_g + l * Dq, ln1_b + l * Dq);

        gemm_kernel<<<dim3(4 * Dq / 64, M / 64), 256>>>(h, f1w, f1b, ff, M, 4 * Dq, Dq, FLAG_RELU);
        gemm_kernel<<<dim3(Dq / 64, M / 64), 256>>>(ff, f2w, f2b, tmp, M, Dq, 4 * Dq, 0);
        add_ln_kernel<<<M, 128>>>(h, tmp, ln2_g + l * Dq, ln2_b + l * Dq);
    }

    pool_kernel<<<(Bq * Dq + 255) / 256, 256>>>(h, pl);
    decoder_kernel<<<1, 256>>>(pl, dec1_w, dec1_b, dec2_w, dec2_b, out);
}

// round 3
// speedup vs baseline: 1.5535x; 1.5535x over previous
#include <cuda_runtime.h>
#include <cuda_bf16.h>
#include <math.h>

#define Bq 4
#define Sq 2048
#define DIN 64
#define Dq 512
#define Hq 8
#define Lq 2
#define NCq 2
#define DKq 64
#define TOPKq 35

#define FLAG_RELU 1
#define FLAG_PE 2

#define NEG_INF (-__int_as_float(0x7f800000))

// ---------------- scratch (device globals; no runtime allocation) ----------------
__device__ float g_h [Bq*Sq*Dq];
__device__ float g_q [Bq*Sq*Dq];
__device__ float g_k [Bq*Sq*Dq];
__device__ float g_v [Bq*Sq*Dq];
__device__ float g_ao[Bq*Sq*Dq];
__device__ float g_tmp[Bq*Sq*Dq];
__device__ float g_ff[Bq*Sq*4*Dq];
__device__ float g_scores[(size_t)Bq*Hq*Sq*Sq];   // 512 MB
__device__ float g_pool[Bq*Dq];
__device__ float g_pe[Sq*Dq];

// ---------------- PE table: pe[s][c], fp32 rounding chain matches reference ----------------
__global__ void pe_kernel(float* __restrict__ pe)
{
    int idx = blockIdx.x * blockDim.x + threadIdx.x;
    if (idx >= Sq * Dq) return;
    int s = idx >> 9, c = idx & 511;
    int half = c >> 1;
    double e = exp((double)(2 * half) * (-9.210340371976184 / 512.0));
    float divf = (float)e;
    float argf = (float)s * divf;
    pe[idx] = (c & 1) ? (float)cos((double)argf) : (float)sin((double)argf);
}

// ---------------- fp32 GEMM: C = A[M,K] @ W[K,N] + bias, 128x128 tile, 8x8 micro ----------------
__global__ void __launch_bounds__(256) gemm_kernel(
    const float* __restrict__ A, const float* __restrict__ W,
    const float* __restrict__ bias, float* __restrict__ C,
    const float* __restrict__ pe,
    int M, int N, int K, int flags)
{
    __shared__ float As[16][132];
    __shared__ float Ws[16][132];
    int tid = threadIdx.x;
    int tx = tid & 15, ty = tid >> 4;
    int row0 = blockIdx.y * 128, col0 = blockIdx.x * 128;

    int ar = tid >> 1, aco = (tid & 1) * 8;       // A: row 0..127, k-offset 0 or 8
    int wr = tid >> 4, wco = (tid & 15) * 8;      // W: k-row 0..15, col-offset

    const float* Abase = A + (size_t)(row0 + ar) * K + aco;
    float4 a0 = *(const float4*)(Abase);
    float4 a1 = *(const float4*)(Abase + 4);
    const float* Wb0 = W + (size_t)wr * N + col0 + wco;
    float4 w0 = *(const float4*)(Wb0);
    float4 w1 = *(const float4*)(Wb0 + 4);

    float acc[8][8] = {};
    int k0 = 0;
    while (true) {
        // regs -> smem (A transposed)
        As[aco+0][ar] = a0.x; As[aco+1][ar] = a0.y; As[aco+2][ar] = a0.z; As[aco+3][ar] = a0.w;
        As[aco+4][ar] = a1.x; As[aco+5][ar] = a1.y; As[aco+6][ar] = a1.z; As[aco+7][ar] = a1.w;
        *(float4*)&Ws[wr][wco]     = w0;
        *(float4*)&Ws[wr][wco + 4] = w1;
        __syncthreads();

        int kn = k0 + 16;
        bool more = kn < K;
        if (more) {
            a0 = *(const float4*)(Abase + kn);
            a1 = *(const float4*)(Abase + kn + 4);
            const float* Wb = W + (size_t)(kn + wr) * N + col0 + wco;
            w0 = *(const float4*)(Wb);
            w1 = *(const float4*)(Wb + 4);
        }

        #pragma unroll
        for (int kk = 0; kk < 16; kk++) {
            float a[8], b[8];
            *(float4*)&a[0] = *(const float4*)&As[kk][ty * 8];
            *(float4*)&a[4] = *(const float4*)&As[kk][ty * 8 + 4];
            *(float4*)&b[0] = *(const float4*)&Ws[kk][tx * 8];
            *(float4*)&b[4] = *(const float4*)&Ws[kk][tx * 8 + 4];
            #pragma unroll
            for (int i = 0; i < 8; i++)
                #pragma unroll
                for (int j = 0; j < 8; j++)
                    acc[i][j] += a[i] * b[j];
        }
        if (!more) break;
        __syncthreads();
        k0 = kn;
    }

    // epilogue
    float bcol[8];
    *(float4*)&bcol[0] = *(const float4*)&bias[col0 + tx * 8];
    *(float4*)&bcol[4] = *(const float4*)&bias[col0 + tx * 8 + 4];
    #pragma unroll
    for (int i = 0; i < 8; i++) {
        int r = row0 + ty * 8 + i;
        float v[8];
        #pragma unroll
        for (int j = 0; j < 8; j++) {
            float t = acc[i][j] + bcol[j];
            if (flags & FLAG_RELU) t = fmaxf(t, 0.0f);
            v[j] = t;
        }
        if (flags & FLAG_PE) {
            const float* per = pe + (size_t)(r & (Sq - 1)) * Dq + col0 + tx * 8;
            float p[8];
            *(float4*)&p[0] = *(const float4*)(per);
            *(float4*)&p[4] = *(const float4*)(per + 4);
            #pragma unroll
            for (int j = 0; j < 8; j++) v[j] += p[j];
        }
        float* Cr = C + (size_t)r * N + col0 + tx * 8;
        *(float4*)(Cr)     = *(float4*)&v[0];
        *(float4*)(Cr + 4) = *(float4*)&v[4];
    }
}

// ---------------- scores: per (b,h)  C[S,S] = q @ k^T * scale, 128x128 tile ----------------
__global__ void __launch_bounds__(256) scores_kernel(
    const float* __restrict__ q, const float* __restrict__ k,
    float* __restrict__ scores)
{
    __shared__ float Qs[32][132];
    __shared__ float Ks[32][132];
    int z = blockIdx.z;
    int b = z >> 3, h = z & 7;
    const float* qb = q + (size_t)b * Sq * Dq + h * DKq;
    const float* kb = k + (size_t)b * Sq * Dq + h * DKq;
    int q0 = blockIdx.y * 128, k0 = blockIdx.x * 128;
    int tid = threadIdx.x;
    int tx = tid & 15, ty = tid >> 4;

    // loader: row 0..127, 4 float4 along d (32 d per slab)
    int lr = tid >> 1, f0 = (tid & 1) * 4;
    const float* Qrow = qb + (size_t)(q0 + lr) * Dq + f0 * 4;
    const float* Krow = kb + (size_t)(k0 + lr) * Dq + f0 * 4;

    float acc[8][8] = {};
    float4 qv[4], kv[4];
    #pragma unroll
    for (int fi = 0; fi < 4; fi++) {
        qv[fi] = *(const float4*)(Qrow + fi * 4);
        kv[fi] = *(const float4*)(Krow + fi * 4);
    }

    #pragma unroll
    for (int d0 = 0; d0 < 64; d0 += 32) {
        #pragma unroll
        for (int fi = 0; fi < 4; fi++) {
            int dd = f0 * 4 + fi * 4;
            Qs[dd+0][lr] = qv[fi].x; Qs[dd+1][lr] = qv[fi].y;
            Qs[dd+2][lr] = qv[fi].z; Qs[dd+3][lr] = qv[fi].w;
            Ks[dd+0][lr] = kv[fi].x; Ks[dd+1][lr] = kv[fi].y;
            Ks[dd+2][lr] = kv[fi].z; Ks[dd+3][lr] = kv[fi].w;
        }
        __syncthreads();
        if (d0 == 0) {
            #pragma unroll
            for (int fi = 0; fi < 4; fi++) {
                qv[fi] = *(const float4*)(Qrow + 32 + fi * 4);
                kv[fi] = *(const float4*)(Krow + 32 + fi * 4);
            }
        }
        #pragma unroll
        for (int kk = 0; kk < 32; kk++) {
            float a[8], bb[8];
            *(float4*)&a[0]  = *(const float4*)&Qs[kk][ty * 8];
            *(float4*)&a[4]  = *(const float4*)&Qs[kk][ty * 8 + 4];
            *(float4*)&bb[0] = *(const float4*)&Ks[kk][tx * 8];
            *(float4*)&bb[4] = *(const float4*)&Ks[kk][tx * 8 + 4];
            #pragma unroll
            for (int i = 0; i < 8; i++)
                #pragma unroll
                for (int j = 0; j < 8; j++)
                    acc[i][j] += a[i] * bb[j];
        }
        if (d0 == 0) __syncthreads();
    }

    float* dst = scores + (size_t)z * Sq * Sq;
    #pragma unroll
    for (int i = 0; i < 8; i++) {
        float v[8];
        #pragma unroll
        for (int j = 0; j < 8; j++) v[j] = acc[i][j] * 0.125f;
        float* row = dst + (size_t)(q0 + ty * 8 + i) * Sq + k0 + tx * 8;
        *(float4*)(row)     = *(float4*)&v[0];
        *(float4*)(row + 4) = *(float4*)&v[4];
    }
}

// ---------------- top-k values (k=35, descending) + softmax + A@V[:35] ----------------
// Only VALUES matter: reference discards indices; equal values => equal weights.
// Each lane keeps a 4-deep sorted register cache of its strided 64-value segment.
__global__ void __launch_bounds__(128) topk_attn_kernel(
    const float* __restrict__ scores, const float* __restrict__ v,
    float* __restrict__ ao)
{
    __shared__ float srow[4][Sq];
    __shared__ float tv[4][TOPKq];
    int w = threadIdx.x >> 5, lane = threadIdx.x & 31;
    int r = blockIdx.x * 4 + w;              // r = (b*H + h)*S + qq
    int qq = r & (Sq - 1);
    int h  = (r >> 11) & 7;
    int b  = r >> 14;
    const float* src = scores + (size_t)r * Sq;
    float* my = &srow[w][0];
    for (int i = lane; i < Sq; i += 32) my[i] = src[i];
    __syncwarp();

    // initial per-lane top-4 of segment {i*32+lane}
    float c0 = NEG_INF, c1 = NEG_INF, c2 = NEG_INF, c3 = NEG_INF;
    #pragma unroll
    for (int i = 0; i < 64; i++) {
        float x = my[i * 32 + lane];
        if (x > c3) {
            if (x > c0)      { c3 = c2; c2 = c1; c1 = c0; c0 = x; }
            else if (x > c1) { c3 = c2; c2 = c1; c1 = x; }
            else if (x > c2) { c3 = c2; c2 = x; }
            else               c3 = x;
        }
    }

    float thr = __int_as_float(0x7f800000);   // +inf
    for (int it = 0; it < TOPKq; it++) {
        float best = c0;
        #pragma unroll
        for (int off = 16; off; off >>= 1)
            best = fmaxf(best, __shfl_xor_sync(0xffffffffu, best, off));
        unsigned bm = __ballot_sync(0xffffffffu, c0 == best);
        int wl = __ffs(bm) - 1;
        if (lane == 0) tv[w][it] = best;
        if (lane == wl) {
            thr = c0;
            c0 = c1; c1 = c2; c2 = c3; c3 = NEG_INF;
            if (c0 == NEG_INF) {
                // refill: top-4 of values strictly below thr
                for (int i = 0; i < 64; i++) {
                    float x = my[i * 32 + lane];
                    if (x < thr && x > c3) {
                        if (x > c0)      { c3 = c2; c2 = c1; c1 = c0; c0 = x; }
                        else if (x > c1) { c3 = c2; c2 = c1; c1 = x; }
                        else if (x > c2) { c3 = c2; c2 = x; }
                        else               c3 = x;
                    }
                }
            }
        }
    }
    __syncwarp();

    // softmax over sorted top-k (max = tv[0])
    float m = tv[w][0];
    float lsum = 0.0f;
    for (int j = lane; j < TOPKq; j += 32) {
        float e = expf(tv[w][j] - m);
        tv[w][j] = e;
        lsum += e;
    }
    __syncwarp();
    #pragma unroll
    for (int off = 16; off; off >>= 1) lsum += __shfl_xor_sync(0xffffffffu, lsum, off);
    float inv = 1.0f / lsum;
    __syncwarp();

    // ao[d] = sum_j attn[j] * v[b, j, h*64 + d]   (V's FIRST 35 rows — source quirk)
    const float* vb = v + (size_t)b * Sq * Dq + h * DKq;
    float a0 = 0.0f, a1 = 0.0f;
    #pragma unroll
    for (int j = 0; j < TOPKq; j++) {
        float a = tv[w][j];
        a0 += a * vb[(size_t)j * Dq + lane];
        a1 += a * vb[(size_t)j * Dq + lane + 32];
    }
    float* dst = ao + (size_t)(b * Sq + qq) * Dq + h * DKq;
    dst[lane]      = a0 * inv;
    dst[lane + 32] = a1 * inv;
}

// ---------------- h = LN(h + add) ----------------
__global__ void __launch_bounds__(128) add_ln_kernel(
    float* __restrict__ hbuf, const float* __restrict__ add,
    const float* __restrict__ g, const float* __restrict__ bta)
{
    int row = blockIdx.x;
    int tid = threadIdx.x;
    const float* hr = hbuf + (size_t)row * Dq;
    const float* ar = add  + (size_t)row * Dq;
    float x[4];
    float s = 0.0f, s2 = 0.0f;
    #pragma unroll
    for (int i = 0; i < 4; i++) {
        float v = hr[tid + i * 128] + ar[tid + i * 128];
        x[i] = v; s += v; s2 += v * v;
    }
    __shared__ float rs[4], rs2[4];
    #pragma unroll
    for (int off = 16; off; off >>= 1) {
        s  += __shfl_xor_sync(0xffffffffu, s, off);
        s2 += __shfl_xor_sync(0xffffffffu, s2, off);
    }
    if ((tid & 31) == 0) { rs[tid >> 5] = s; rs2[tid >> 5] = s2; }
    __syncthreads();
    s  = rs[0] + rs[1] + rs[2] + rs[3];
    s2 = rs2[0] + rs2[1] + rs2[2] + rs2[3];
    float mean = s * (1.0f / Dq);
    float var  = s2 * (1.0f / Dq) - mean * mean;
    float invs = rsqrtf(var + 1e-5f);
    float* out = hbuf + (size_t)row * Dq;
    #pragma unroll
    for (int i = 0; i < 4; i++) {
        int c = tid + i * 128;
        out[c] = (x[i] - mean) * invs * g[c] + bta[c];
    }
}

// ---------------- pooled[b,d] = mean_s h[b,s,d] ----------------
__global__ void pool_kernel(const float* __restrict__ h, float* __restrict__ pool)
{
    int idx = blockIdx.x * blockDim.x + threadIdx.x;
    if (idx >= Bq * Dq) return;
    int b = idx >> 9, d = idx & 511;
    const float* p = h + (size_t)b * Sq * Dq + d;
    float s[8] = {};
    for (int i = 0; i < Sq; i += 8) {
        #pragma unroll
        for (int u = 0; u < 8; u++) s[u] += p[(size_t)(i + u) * Dq];
    }
    float t = ((s[0] + s[1]) + (s[2] + s[3])) + ((s[4] + s[5]) + (s[6] + s[7]));
    pool[idx] = t * (1.0f / Sq);
}

// ---------------- decoder: out = relu(pool@W1+b1)@W2+b2 ----------------
__global__ void __launch_bounds__(256) decoder_kernel(
    const float* __restrict__ pool,
    const float* __restrict__ w1, const float* __restrict__ b1,
    const float* __restrict__ w2, const float* __restrict__ b2,
    float* __restrict__ out)
{
    __shared__ float ps[Bq * Dq];
    __shared__ float tmp[Bq * 256];
    int tid = threadIdx.x;
    for (int i = tid; i < Bq * Dq; i += 256) ps[i] = pool[i];
    __syncthreads();
    #pragma unroll
    for (int e = 0; e < 4; e++) {
        int idx = tid + e * 256;
        int bi = idx >> 8, j = idx & 255;
        float acc = b1[j];
        for (int k = 0; k < Dq; k++) acc += ps[bi * Dq + k] * w1[k * 256 + j];
        tmp[idx] = fmaxf(acc, 0.0f);
    }
    __syncthreads();
    if (tid < Bq * NCq) {
        int bi = tid / NCq, c = tid % NCq;
        float acc = b2[c];
        for (int j = 0; j < 256; j++) acc += tmp[bi * 256 + j] * w2[j * NCq + c];
        out[tid] = acc;
    }
}

// ---------------- launch ----------------
extern "C" void kernel_launch(void* const* d_in, const int* in_sizes, int n_in,
                              void* d_out, int out_size)
{
    const float* x      = (const float*)d_in[0];
    const float* emb_w  = (const float*)d_in[1];
    const float* emb_b  = (const float*)d_in[2];
    const float* wq     = (const float*)d_in[3];
    const float* bq     = (const float*)d_in[4];
    const float* wk     = (const float*)d_in[5];
    const float* bk     = (const float*)d_in[6];
    const float* wv     = (const float*)d_in[7];
    const float* bv     = (const float*)d_in[8];
    const float* wo     = (const float*)d_in[9];
    const float* bo     = (const float*)d_in[10];
    const float* ff1_w  = (const float*)d_in[11];
    const float* ff1_b  = (const float*)d_in[12];
    const float* ff2_w  = (const float*)d_in[13];
    const float* ff2_b  = (const float*)d_in[14];
    const float* ln1_g  = (const float*)d_in[15];
    const float* ln1_b  = (const float*)d_in[16];
    const float* ln2_g  = (const float*)d_in[17];
    const float* ln2_b  = (const float*)d_in[18];
    const float* dec1_w = (const float*)d_in[19];
    const float* dec1_b = (const float*)d_in[20];
    const float* dec2_w = (const float*)d_in[21];
    const float* dec2_b = (const float*)d_in[22];
    float* out = (float*)d_out;

    float *h, *q, *k, *v, *ao, *tmp, *ff, *sc, *pl, *pe;
    cudaGetSymbolAddress((void**)&h,   g_h);
    cudaGetSymbolAddress((void**)&q,   g_q);
    cudaGetSymbolAddress((void**)&k,   g_k);
    cudaGetSymbolAddress((void**)&v,   g_v);
    cudaGetSymbolAddress((void**)&ao,  g_ao);
    cudaGetSymbolAddress((void**)&tmp, g_tmp);
    cudaGetSymbolAddress((void**)&ff,  g_ff);
    cudaGetSymbolAddress((void**)&sc,  g_scores);
    cudaGetSymbolAddress((void**)&pl,  g_pool);
    cudaGetSymbolAddress((void**)&pe,  g_pe);

    const int M = Bq * Sq;   // 8192

    pe_kernel<<<(Sq * Dq + 255) / 256, 256>>>(pe);

    // embedding + positional encoding
    gemm_kernel<<<dim3(Dq / 128, M / 128), 256>>>(x, emb_w, emb_b, h, pe, M, Dq, DIN, FLAG_PE);

    for (int l = 0; l < Lq; l++) {
        const float* wq_l = wq + (size_t)l * Dq * Dq;
        const float* wk_l = wk + (size_t)l * Dq * Dq;
        const float* wv_l = wv + (size_t)l * Dq * Dq;
        const float* wo_l = wo + (size_t)l * Dq * Dq;
        const float* bq_l = bq + l * Dq;
        const float* bk_l = bk + l * Dq;
        const float* bv_l = bv + l * Dq;
        const float* bo_l = bo + l * Dq;
        const float* f1w  = ff1_w + (size_t)l * Dq * 4 * Dq;
        const float* f1b  = ff1_b + l * 4 * Dq;
        const float* f2w  = ff2_w + (size_t)l * 4 * Dq * Dq;
        const float* f2b  = ff2_b + l * Dq;

        gemm_kernel<<<dim3(Dq / 128, M / 128), 256>>>(h, wq_l, bq_l, q, pe, M, Dq, Dq, 0);
        gemm_kernel<<<dim3(Dq / 128, M / 128), 256>>>(h, wk_l, bk_l, k, pe, M, Dq, Dq, 0);
        gemm_kernel<<<dim3(Dq / 128, M / 128), 256>>>(h, wv_l, bv_l, v, pe, M, Dq, Dq, 0);

        scores_kernel<<<dim3(Sq / 128, Sq / 128, Bq * Hq), 256>>>(q, k, sc);
        topk_attn_kernel<<<(Bq * Hq * Sq) / 4, 128>>>(sc, v, ao);

        gemm_kernel<<<dim3(Dq / 128, M / 128), 256>>>(ao, wo_l, bo_l, tmp, pe, M, Dq, Dq, 0);
        add_ln_kernel<<<M, 128>>>(h, tmp, ln1_g + l * Dq, ln1_b + l * Dq);

        gemm_kernel<<<dim3(4 * Dq / 128, M / 128), 256>>>(h, f1w, f1b, ff, pe, M, 4 * Dq, Dq, FLAG_RELU);
        gemm_kernel<<<dim3(Dq / 128, M / 128), 256>>>(ff, f2w, f2b, tmp, pe, M, Dq, 4 * Dq, 0);
        add_ln_kernel<<<M, 128>>>(h, tmp, ln2_g + l * Dq, ln2_b + l * Dq);
    }

    pool_kernel<<<(Bq * Dq + 255) / 256, 256>>>(h, pl);
    decoder_kernel<<<1, 256>>>(pl, dec1_w, dec1_b, dec2_w, dec2_b, out);
}